// round 2
// baseline (speedup 1.0000x reference)
#include <cuda_runtime.h>
#include <cuda_bf16.h>
#include <math.h>

#define N_NODES 100000
#define IN_DIM  128
#define HID     64
#define NCLS    40

// Scratch buffers (alloc-free rule: __device__ globals)
__device__ float g_A[(size_t)N_NODES * HID];
__device__ float g_B[(size_t)N_NODES * HID];

// ---------------------------------------------------------------------------
// zero fill (float4)
// ---------------------------------------------------------------------------
__global__ void zero_kernel(float* __restrict__ p, int n4) {
    int i = blockIdx.x * blockDim.x + threadIdx.x;
    if (i < n4) reinterpret_cast<float4*>(p)[i] = make_float4(0.f, 0.f, 0.f, 0.f);
}

// ---------------------------------------------------------------------------
// Tiled GEMM: C[N,64] = act(X[N,K]) @ W[K,64] + b
// 64x64 tile, 128 threads, thread tile 4 rows x 8 cols, K chunked by 32.
// Xs padded to stride 36 floats (144B, 16B-aligned, bank-conflict-free).
// ---------------------------------------------------------------------------
template<int K, bool RELU>
__global__ void gemm64_kernel(const float* __restrict__ X,
                              const float* __restrict__ W,
                              const float* __restrict__ b,
                              float* __restrict__ C, int N) {
    constexpr int BK = 32;
    __shared__ float Xs[64][BK + 4];   // stride 36 floats = 144B (aligned, bank-shift 4)
    __shared__ float Ws[BK][64];

    const int tid = threadIdx.x;       // 128 threads
    const int tx  = tid & 7;           // col group: cols tx*8 .. tx*8+7
    const int ty  = tid >> 3;          // row group: rows ty*4 .. ty*4+3
    const int nodeBase = blockIdx.x * 64;

    float acc[4][8];
    const float4 bv0 = *reinterpret_cast<const float4*>(b + tx * 8);
    const float4 bv1 = *reinterpret_cast<const float4*>(b + tx * 8 + 4);
#pragma unroll
    for (int i = 0; i < 4; i++) {
        acc[i][0] = bv0.x; acc[i][1] = bv0.y; acc[i][2] = bv0.z; acc[i][3] = bv0.w;
        acc[i][4] = bv1.x; acc[i][5] = bv1.y; acc[i][6] = bv1.z; acc[i][7] = bv1.w;
    }

    for (int kc = 0; kc < K; kc += BK) {
        // X tile: 64 rows x 32 cols = 512 float4, 4 per thread (coalesced).
#pragma unroll
        for (int t = 0; t < 4; t++) {
            int idx = tid + t * 128;          // 0..511
            int r   = idx >> 3;               // 0..63
            int c4  = idx & 7;                // 0..7
            int node = nodeBase + r;
            float4 xv = make_float4(0.f, 0.f, 0.f, 0.f);
            if (node < N)
                xv = *reinterpret_cast<const float4*>(X + (size_t)node * K + kc + c4 * 4);
            if (RELU) {
                xv.x = fmaxf(xv.x, 0.f); xv.y = fmaxf(xv.y, 0.f);
                xv.z = fmaxf(xv.z, 0.f); xv.w = fmaxf(xv.w, 0.f);
            }
            *reinterpret_cast<float4*>(&Xs[r][c4 * 4]) = xv;
        }
        // W chunk: 32 rows x 64 cols = 512 float4, 4 per thread.
#pragma unroll
        for (int t = 0; t < 4; t++) {
            int idx = tid + t * 128;
            int r   = idx >> 4;               // 0..31
            int c4  = idx & 15;               // 0..15
            *reinterpret_cast<float4*>(&Ws[r][c4 * 4]) =
                *reinterpret_cast<const float4*>(W + (size_t)(kc + r) * 64 + c4 * 4);
        }
        __syncthreads();

#pragma unroll
        for (int kk = 0; kk < BK; kk++) {
            const float4 wv0 = *reinterpret_cast<const float4*>(&Ws[kk][tx * 8]);
            const float4 wv1 = *reinterpret_cast<const float4*>(&Ws[kk][tx * 8 + 4]);
            float xv[4];
#pragma unroll
            for (int i = 0; i < 4; i++) xv[i] = Xs[ty * 4 + i][kk];
#pragma unroll
            for (int i = 0; i < 4; i++) {
                acc[i][0] += xv[i] * wv0.x;
                acc[i][1] += xv[i] * wv0.y;
                acc[i][2] += xv[i] * wv0.z;
                acc[i][3] += xv[i] * wv0.w;
                acc[i][4] += xv[i] * wv1.x;
                acc[i][5] += xv[i] * wv1.y;
                acc[i][6] += xv[i] * wv1.z;
                acc[i][7] += xv[i] * wv1.w;
            }
        }
        __syncthreads();
    }

#pragma unroll
    for (int i = 0; i < 4; i++) {
        int node = nodeBase + ty * 4 + i;
        if (node < N) {
            float4 o0 = make_float4(acc[i][0], acc[i][1], acc[i][2], acc[i][3]);
            float4 o1 = make_float4(acc[i][4], acc[i][5], acc[i][6], acc[i][7]);
            *reinterpret_cast<float4*>(C + (size_t)node * 64 + tx * 8)     = o0;
            *reinterpret_cast<float4*>(C + (size_t)node * 64 + tx * 8 + 4) = o1;
        }
    }
}

// ---------------------------------------------------------------------------
// SpMM: out[row[e], :] += val[e] * dense[col[e], :]   (64 cols)
// Warp loads 32 edges' metadata coalesced, then processes 2 edges per
// iteration: half-warp per edge, lane owns one float4 (16 x 16B = full row).
// One LDG.128 + one red.global.add.v4.f32 per half-warp per edge.
// ---------------------------------------------------------------------------
__global__ void spmm_kernel(const int* __restrict__ er, const int* __restrict__ ec,
                            const float* __restrict__ ev,
                            const float* __restrict__ D,
                            float* __restrict__ O, int E) {
    const int lane   = threadIdx.x & 31;
    const int warpId = (blockIdx.x * blockDim.x + threadIdx.x) >> 5;
    const int base   = warpId * 32;
    if (base >= E) return;

    const int g     = lane >> 4;      // which edge of the pair
    const int chunk = lane & 15;      // float4 index within the 64-float row

    int   r = 0, c = 0;
    float v = 0.f;
    const int e = base + lane;
    if (e < E) { r = er[e]; c = ec[e]; v = ev[e]; }
    const int cnt = min(32, E - base);

    for (int i = 0; i < cnt; i += 2) {
        const int idx = i + g;
        const int   ri = __shfl_sync(0xffffffffu, r, idx);
        const int   ci = __shfl_sync(0xffffffffu, c, idx);
        const float vi = __shfl_sync(0xffffffffu, v, idx);

        if (idx < cnt) {
            const float4 a = *(reinterpret_cast<const float4*>(D + (size_t)ci * 64) + chunk);
            float4* dst    =   reinterpret_cast<float4*>(O + (size_t)ri * 64) + chunk;
            const float mx = vi * a.x, my = vi * a.y, mz = vi * a.z, mw = vi * a.w;
            asm volatile("red.global.add.v4.f32 [%0], {%1, %2, %3, %4};"
                         :: "l"(dst), "f"(mx), "f"(my), "f"(mz), "f"(mw)
                         : "memory");
        }
    }
}

// ---------------------------------------------------------------------------
// Classifier: out = log_softmax(H @ Wc + bc), one warp per node.
// ---------------------------------------------------------------------------
__global__ void classifier_kernel(const float* __restrict__ H,
                                  const float* __restrict__ Wc,
                                  const float* __restrict__ bc,
                                  float* __restrict__ out, int N) {
    __shared__ float Ws[64 * 40 + 64];   // padded so lane>=8 dummy column stays in-bounds
    __shared__ float bs[40];
    __shared__ float hs[8][64];

    const int tid  = threadIdx.x;
    const int lane = tid & 31;
    const int warp = tid >> 5;

    for (int i = tid; i < 64 * 40; i += 256) Ws[i] = Wc[i];
    for (int i = 64 * 40 + tid; i < 64 * 40 + 64; i += 256) Ws[i] = 0.f;
    if (tid < 40) bs[tid] = bc[tid];
    __syncthreads();

    for (int it = 0; it < 4; it++) {
        const int node = blockIdx.x * 32 + it * 8 + warp;
        if (node < N) {
            __syncwarp();
            hs[warp][lane]      = H[(size_t)node * 64 + lane];
            hs[warp][lane + 32] = H[(size_t)node * 64 + lane + 32];
            __syncwarp();

            float v0 = bs[lane];
            float v1 = (lane < 8) ? bs[32 + lane] : 0.f;
#pragma unroll
            for (int k = 0; k < 64; k++) {
                const float h = hs[warp][k];
                v0 += h * Ws[k * 40 + lane];
                v1 += h * Ws[k * 40 + 32 + lane];
            }

            float m = (lane < 8) ? fmaxf(v0, v1) : v0;
#pragma unroll
            for (int off = 16; off; off >>= 1)
                m = fmaxf(m, __shfl_xor_sync(0xffffffffu, m, off));
            float s = expf(v0 - m) + ((lane < 8) ? expf(v1 - m) : 0.f);
#pragma unroll
            for (int off = 16; off; off >>= 1)
                s += __shfl_xor_sync(0xffffffffu, s, off);
            const float lse = m + logf(s);

            out[(size_t)node * 40 + lane] = v0 - lse;
            if (lane < 8)
                out[(size_t)node * 40 + 32 + lane] = v1 - lse;
        }
    }
}

// ---------------------------------------------------------------------------
// launch
// ---------------------------------------------------------------------------
extern "C" void kernel_launch(void* const* d_in, const int* in_sizes, int n_in,
                              void* d_out, int out_size) {
    const float* x  = (const float*)d_in[0];
    const int*   er = (const int*)  d_in[1];
    const int*   ec = (const int*)  d_in[2];
    const float* ev = (const float*)d_in[3];
    const float* W1 = (const float*)d_in[4];
    const float* b1 = (const float*)d_in[5];
    const float* W2 = (const float*)d_in[6];
    const float* b2 = (const float*)d_in[7];
    const float* Wc = (const float*)d_in[8];
    const float* bc = (const float*)d_in[9];
    float* out = (float*)d_out;

    const int N = in_sizes[0] / IN_DIM;   // 100000
    const int E = in_sizes[1];            // 1600000

    void* pA_ = nullptr; void* pB_ = nullptr;
    cudaGetSymbolAddress(&pA_, g_A);
    cudaGetSymbolAddress(&pB_, g_B);
    float* A = (float*)pA_;
    float* B = (float*)pB_;

    const int gemmBlocks  = (N + 63) / 64;
    const int zeroN4      = (N * HID) / 4;
    const int zeroBlocks  = (zeroN4 + 255) / 256;
    const int spmmWarps   = (E + 31) / 32;
    const int spmmBlocks  = (spmmWarps + 7) / 8;
    const int clsBlocks   = (N + 31) / 32;

    // Layer 1
    gemm64_kernel<IN_DIM, false><<<gemmBlocks, 128>>>(x, W1, b1, A, N);
    zero_kernel<<<zeroBlocks, 256>>>(B, zeroN4);
    spmm_kernel<<<spmmBlocks, 256>>>(er, ec, ev, A, B, E);

    // Layer 2 (relu fused into GEMM read)
    gemm64_kernel<HID, true><<<gemmBlocks, 128>>>(B, W2, b2, A, N);
    zero_kernel<<<zeroBlocks, 256>>>(B, zeroN4);
    spmm_kernel<<<spmmBlocks, 256>>>(er, ec, ev, A, B, E);

    // Classifier + log-softmax
    classifier_kernel<<<clsBlocks, 256>>>(B, Wc, bc, out, N);
}

// round 3
// speedup vs baseline: 1.1542x; 1.1542x over previous
#include <cuda_runtime.h>
#include <cuda_bf16.h>
#include <math.h>

#define N_NODES 100000
#define IN_DIM  128
#define HID     64
#define NCLS    40
#define N_EDGES 1600000
#define CHUNK   512
#define NCHUNK  ((N_NODES + CHUNK - 1) / CHUNK)   // 196

// Scratch (__device__ globals per alloc-free rule)
__device__ float g_A[(size_t)N_NODES * HID];
__device__ float g_B[(size_t)N_NODES * HID];
__device__ int   g_cnt[N_NODES];
__device__ int   g_ptr[N_NODES + 1];
__device__ int   g_cur[N_NODES];
__device__ int   g_chunkOff[NCHUNK];
__device__ int2  g_csr[N_EDGES];

// ---------------------------------------------------------------------------
// CSR construction
// ---------------------------------------------------------------------------
__global__ void zero_int_kernel(int* __restrict__ p, int n) {
    int i = blockIdx.x * blockDim.x + threadIdx.x;
    if (i < n) p[i] = 0;
}

__global__ void hist_kernel(const int* __restrict__ er, int* __restrict__ cnt, int E) {
    int e = blockIdx.x * blockDim.x + threadIdx.x;
    if (e < E) atomicAdd(&cnt[er[e]], 1);
}

// per-chunk sums
__global__ void chunk_reduce_kernel(const int* __restrict__ cnt, int* __restrict__ partials, int N) {
    __shared__ int s[CHUNK];
    int t = threadIdx.x;
    int i = blockIdx.x * CHUNK + t;
    s[t] = (i < N) ? cnt[i] : 0;
    __syncthreads();
    for (int off = CHUNK / 2; off > 0; off >>= 1) {
        if (t < off) s[t] += s[t + off];
        __syncthreads();
    }
    if (t == 0) partials[blockIdx.x] = s[0];
}

// exclusive scan over NCHUNK partials (single block)
__global__ void scan_partials_kernel(const int* __restrict__ partials, int* __restrict__ chunkOff) {
    __shared__ int s[256];
    int t = threadIdx.x;
    s[t] = (t < NCHUNK) ? partials[t] : 0;
    __syncthreads();
#pragma unroll
    for (int off = 1; off < 256; off <<= 1) {
        int x = (t >= off) ? s[t - off] : 0;
        __syncthreads();
        s[t] += x;
        __syncthreads();
    }
    if (t < NCHUNK) chunkOff[t] = s[t] - partials[t];   // exclusive
}

// per-chunk exclusive scan + offset -> row_ptr, cursor
__global__ void block_scan_kernel(const int* __restrict__ cnt,
                                  const int* __restrict__ chunkOff,
                                  int* __restrict__ ptr, int* __restrict__ cur,
                                  int N, int E) {
    __shared__ int s[CHUNK];
    int t = threadIdx.x;
    int i = blockIdx.x * CHUNK + t;
    int c = (i < N) ? cnt[i] : 0;
    s[t] = c;
    __syncthreads();
#pragma unroll
    for (int off = 1; off < CHUNK; off <<= 1) {
        int x = (t >= off) ? s[t - off] : 0;
        __syncthreads();
        s[t] += x;
        __syncthreads();
    }
    if (i < N) {
        int start = chunkOff[blockIdx.x] + s[t] - c;   // exclusive
        ptr[i] = start;
        cur[i] = start;
        if (i == N - 1) ptr[N] = E;
    }
}

__global__ void scatter_kernel(const int* __restrict__ er, const int* __restrict__ ec,
                               const float* __restrict__ ev,
                               int* __restrict__ cur, int2* __restrict__ csr, int E) {
    int e = blockIdx.x * blockDim.x + threadIdx.x;
    if (e < E) {
        int pos = atomicAdd(&cur[er[e]], 1);
        csr[pos] = make_int2(ec[e], __float_as_int(ev[e]));
    }
}

// ---------------------------------------------------------------------------
// CSR SpMM: O[r,:] = sum_e val * D[col,:], no atomics, no pre-zero.
// Half-warp per row; lane owns one float4 of the 64-float row.
// ---------------------------------------------------------------------------
__global__ void csr_spmm_kernel(const int* __restrict__ ptr, const int2* __restrict__ csr,
                                const float* __restrict__ D, float* __restrict__ O, int N) {
    const int lane = threadIdx.x & 31;
    const int g = lane >> 4;          // half index (row select)
    const int h = lane & 15;          // float4 chunk within row
    const int warpId = (blockIdx.x * blockDim.x + threadIdx.x) >> 5;
    const int row = warpId * 2 + g;

    int start = 0, n = 0;
    if (row < N) { start = ptr[row]; n = ptr[row + 1] - start; }
    const int nOther = __shfl_xor_sync(0xffffffffu, n, 16);
    const int nMax = max(n, nOther);

    float4 acc = make_float4(0.f, 0.f, 0.f, 0.f);
    for (int base = 0; base < nMax; base += 16) {
        const int j = base + h;
        int2 meta = make_int2(0, 0);
        if (j < n) meta = csr[start + j];
#pragma unroll
        for (int jj = 0; jj < 16; jj++) {
            if (base + jj >= nMax) break;                       // uniform across warp
            const int   ci = __shfl_sync(0xffffffffu, meta.x, (g << 4) | jj);
            const float vi = __int_as_float(__shfl_sync(0xffffffffu, meta.y, (g << 4) | jj));
            if (base + jj < n) {
                const float4 a = *(reinterpret_cast<const float4*>(D + (size_t)ci * 64) + h);
                acc.x += vi * a.x; acc.y += vi * a.y;
                acc.z += vi * a.z; acc.w += vi * a.w;
            }
        }
    }
    if (row < N)
        *(reinterpret_cast<float4*>(O + (size_t)row * 64) + h) = acc;
}

// ---------------------------------------------------------------------------
// Tiled GEMM (R1 shape, conflict-free smem): C = act(X)@W + b
// 64x64 tile, 256 threads, 4x4 per thread, Xs stride 33.
// ---------------------------------------------------------------------------
template<int K, bool RELU>
__global__ void gemm64_kernel(const float* __restrict__ X,
                              const float* __restrict__ W,
                              const float* __restrict__ b,
                              float* __restrict__ C, int N) {
    constexpr int BK = 32;
    __shared__ float Xs[64][BK + 1];   // stride 33: row-step 4 -> bank shift 4
    __shared__ float Ws[BK][64];

    const int tid = threadIdx.x;
    const int tx = tid & 15;
    const int ty = tid >> 4;
    const int nodeBase = blockIdx.x * 64;

    float acc[4][4];
    const float4 bv = *reinterpret_cast<const float4*>(b + tx * 4);
#pragma unroll
    for (int i = 0; i < 4; i++) {
        acc[i][0] = bv.x; acc[i][1] = bv.y; acc[i][2] = bv.z; acc[i][3] = bv.w;
    }

    for (int kc = 0; kc < K; kc += BK) {
#pragma unroll
        for (int t = 0; t < 2; t++) {
            int idx = tid + t * 256;          // 0..511
            int r   = idx >> 3;               // 0..63
            int c4  = idx & 7;                // 0..7
            int node = nodeBase + r;
            float4 xv = make_float4(0.f, 0.f, 0.f, 0.f);
            if (node < N)
                xv = *reinterpret_cast<const float4*>(X + (size_t)node * K + kc + c4 * 4);
            if (RELU) {
                xv.x = fmaxf(xv.x, 0.f); xv.y = fmaxf(xv.y, 0.f);
                xv.z = fmaxf(xv.z, 0.f); xv.w = fmaxf(xv.w, 0.f);
            }
            // scalar stores (stride 33 unaligned for float4); banks r+4*c4: perm of 0..31
            Xs[r][c4 * 4 + 0] = xv.x;
            Xs[r][c4 * 4 + 1] = xv.y;
            Xs[r][c4 * 4 + 2] = xv.z;
            Xs[r][c4 * 4 + 3] = xv.w;
        }
#pragma unroll
        for (int t = 0; t < 2; t++) {
            int idx = tid + t * 256;
            int r   = idx >> 4;               // 0..31
            int c4  = idx & 15;               // 0..15
            *reinterpret_cast<float4*>(&Ws[r][c4 * 4]) =
                *reinterpret_cast<const float4*>(W + (size_t)(kc + r) * 64 + c4 * 4);
        }
        __syncthreads();

#pragma unroll
        for (int kk = 0; kk < BK; kk++) {
            const float4 wv = *reinterpret_cast<const float4*>(&Ws[kk][tx * 4]);
            float xv[4];
#pragma unroll
            for (int i = 0; i < 4; i++) xv[i] = Xs[ty * 4 + i][kk];
#pragma unroll
            for (int i = 0; i < 4; i++) {
                acc[i][0] += xv[i] * wv.x;
                acc[i][1] += xv[i] * wv.y;
                acc[i][2] += xv[i] * wv.z;
                acc[i][3] += xv[i] * wv.w;
            }
        }
        __syncthreads();
    }

#pragma unroll
    for (int i = 0; i < 4; i++) {
        int node = nodeBase + ty * 4 + i;
        if (node < N) {
            float4 o = make_float4(acc[i][0], acc[i][1], acc[i][2], acc[i][3]);
            *reinterpret_cast<float4*>(C + (size_t)node * 64 + tx * 4) = o;
        }
    }
}

// ---------------------------------------------------------------------------
// Classifier: out = log_softmax(H @ Wc + bc), one warp per node.
// ---------------------------------------------------------------------------
__global__ void classifier_kernel(const float* __restrict__ H,
                                  const float* __restrict__ Wc,
                                  const float* __restrict__ bc,
                                  float* __restrict__ out, int N) {
    __shared__ float Ws[64 * 40 + 64];
    __shared__ float bs[40];
    __shared__ float hs[8][64];

    const int tid  = threadIdx.x;
    const int lane = tid & 31;
    const int warp = tid >> 5;

    for (int i = tid; i < 64 * 40; i += 256) Ws[i] = Wc[i];
    for (int i = 64 * 40 + tid; i < 64 * 40 + 64; i += 256) Ws[i] = 0.f;
    if (tid < 40) bs[tid] = bc[tid];
    __syncthreads();

    for (int it = 0; it < 4; it++) {
        const int node = blockIdx.x * 32 + it * 8 + warp;
        if (node < N) {
            __syncwarp();
            hs[warp][lane]      = H[(size_t)node * 64 + lane];
            hs[warp][lane + 32] = H[(size_t)node * 64 + lane + 32];
            __syncwarp();

            float v0 = bs[lane];
            float v1 = (lane < 8) ? bs[32 + lane] : 0.f;
#pragma unroll
            for (int k = 0; k < 64; k++) {
                const float h = hs[warp][k];
                v0 += h * Ws[k * 40 + lane];
                v1 += h * Ws[k * 40 + 32 + lane];
            }

            float m = (lane < 8) ? fmaxf(v0, v1) : v0;
#pragma unroll
            for (int off = 16; off; off >>= 1)
                m = fmaxf(m, __shfl_xor_sync(0xffffffffu, m, off));
            float s = expf(v0 - m) + ((lane < 8) ? expf(v1 - m) : 0.f);
#pragma unroll
            for (int off = 16; off; off >>= 1)
                s += __shfl_xor_sync(0xffffffffu, s, off);
            const float lse = m + logf(s);

            out[(size_t)node * 40 + lane] = v0 - lse;
            if (lane < 8)
                out[(size_t)node * 40 + 32 + lane] = v1 - lse;
        }
    }
}

// ---------------------------------------------------------------------------
// launch
// ---------------------------------------------------------------------------
extern "C" void kernel_launch(void* const* d_in, const int* in_sizes, int n_in,
                              void* d_out, int out_size) {
    const float* x  = (const float*)d_in[0];
    const int*   er = (const int*)  d_in[1];
    const int*   ec = (const int*)  d_in[2];
    const float* ev = (const float*)d_in[3];
    const float* W1 = (const float*)d_in[4];
    const float* b1 = (const float*)d_in[5];
    const float* W2 = (const float*)d_in[6];
    const float* b2 = (const float*)d_in[7];
    const float* Wc = (const float*)d_in[8];
    const float* bc = (const float*)d_in[9];
    float* out = (float*)d_out;

    const int N = in_sizes[0] / IN_DIM;   // 100000
    const int E = in_sizes[1];            // 1600000

    void *pA_, *pB_, *pCnt_, *pPtr_, *pCur_, *pOff_, *pCsr_;
    cudaGetSymbolAddress(&pA_, g_A);
    cudaGetSymbolAddress(&pB_, g_B);
    cudaGetSymbolAddress(&pCnt_, g_cnt);
    cudaGetSymbolAddress(&pPtr_, g_ptr);
    cudaGetSymbolAddress(&pCur_, g_cur);
    cudaGetSymbolAddress(&pOff_, g_chunkOff);
    cudaGetSymbolAddress(&pCsr_, g_csr);
    float* A   = (float*)pA_;
    float* B   = (float*)pB_;
    int*   cnt = (int*)pCnt_;
    int*   ptr = (int*)pPtr_;
    int*   cur = (int*)pCur_;
    int*   off = (int*)pOff_;
    int2*  csr = (int2*)pCsr_;

    const int gemmBlocks = (N + 63) / 64;
    const int eBlocks    = (E + 255) / 256;
    const int spmmBlocks = (N + 15) / 16;      // 16 rows per 256-thread block
    const int clsBlocks  = (N + 31) / 32;

    // --- CSR build (per launch; no caching) ---
    zero_int_kernel<<<(N + 255) / 256, 256>>>(cnt, N);
    hist_kernel<<<eBlocks, 256>>>(er, cnt, E);
    chunk_reduce_kernel<<<NCHUNK, CHUNK>>>(cnt, off /*reuse as partials*/, N);
    // off currently holds partials; scan in-place into chunk offsets via cur? use two stages:
    scan_partials_kernel<<<1, 256>>>(off, cur /*borrow as chunkOff*/);
    block_scan_kernel<<<NCHUNK, CHUNK>>>(cnt, cur, ptr, cnt /*cursor reuses cnt*/, N, E);
    scatter_kernel<<<eBlocks, 256>>>(er, ec, ev, cnt, csr, E);

    // --- Layer 1 ---
    gemm64_kernel<IN_DIM, false><<<gemmBlocks, 256>>>(x, W1, b1, A, N);
    csr_spmm_kernel<<<spmmBlocks, 256>>>(ptr, csr, A, B, N);

    // --- Layer 2 (relu fused into GEMM read) ---
    gemm64_kernel<HID, true><<<gemmBlocks, 256>>>(B, W2, b2, A, N);
    csr_spmm_kernel<<<spmmBlocks, 256>>>(ptr, csr, A, B, N);

    // --- Classifier + log-softmax ---
    classifier_kernel<<<clsBlocks, 256>>>(B, Wc, bc, out, N);
}

// round 4
// speedup vs baseline: 1.3238x; 1.1470x over previous
#include <cuda_runtime.h>
#include <cuda_bf16.h>
#include <math.h>

#define N_NODES 100000
#define IN_DIM  128
#define HID     64
#define NCLS    40
#define N_EDGES 1600000
#define CHUNK   512
#define NCHUNK  ((N_NODES + CHUNK - 1) / CHUNK)   // 196

// Scratch (__device__ globals per alloc-free rule)
__device__ float g_A[(size_t)N_NODES * HID];
__device__ float g_B[(size_t)N_NODES * HID];
__device__ int   g_cnt[N_NODES];
__device__ int   g_ptr[N_NODES + 1];
__device__ int   g_partials[NCHUNK];
__device__ int2  g_csr[N_EDGES];

// ---------------------------------------------------------------------------
// CSR construction
// ---------------------------------------------------------------------------
__global__ void zero_int_kernel(int* __restrict__ p, int n) {
    int i = blockIdx.x * blockDim.x + threadIdx.x;
    if (i < n) p[i] = 0;
}

__global__ void hist_kernel(const int* __restrict__ er, int* __restrict__ cnt, int E) {
    int e = blockIdx.x * blockDim.x + threadIdx.x;
    if (e < E) atomicAdd(&cnt[er[e]], 1);
}

// per-chunk sums
__global__ void chunk_reduce_kernel(const int* __restrict__ cnt, int* __restrict__ partials, int N) {
    __shared__ int s[CHUNK];
    int t = threadIdx.x;
    int i = blockIdx.x * CHUNK + t;
    s[t] = (i < N) ? cnt[i] : 0;
    __syncthreads();
    for (int off = CHUNK / 2; off > 0; off >>= 1) {
        if (t < off) s[t] += s[t + off];
        __syncthreads();
    }
    if (t == 0) partials[blockIdx.x] = s[0];
}

// per-chunk exclusive scan; each block redundantly scans the 196 partials
// in smem (cheap) to get its chunk offset -> writes ptr and cursor.
__global__ void block_scan_kernel(const int* __restrict__ cnt,
                                  const int* __restrict__ partials,
                                  int* __restrict__ ptr, int* __restrict__ cur,
                                  int N, int E) {
    __shared__ int s[CHUNK];
    __shared__ int p[256];
    int t = threadIdx.x;

    if (t < 256) p[t] = (t < NCHUNK) ? partials[t] : 0;
    __syncthreads();
#pragma unroll
    for (int off = 1; off < 256; off <<= 1) {
        int x = (t < 256 && t >= off) ? p[t - off] : 0;
        __syncthreads();
        if (t < 256) p[t] += x;      // inclusive scan of partials
        __syncthreads();
    }
    const int chunkOff = (blockIdx.x == 0) ? 0 : p[blockIdx.x - 1];

    int i = blockIdx.x * CHUNK + t;
    int c = (i < N) ? cnt[i] : 0;
    s[t] = c;
    __syncthreads();
#pragma unroll
    for (int off = 1; off < CHUNK; off <<= 1) {
        int x = (t >= off) ? s[t - off] : 0;
        __syncthreads();
        s[t] += x;
        __syncthreads();
    }
    if (i < N) {
        int start = chunkOff + s[t] - c;   // exclusive
        ptr[i] = start;
        cur[i] = start;
        if (i == N - 1) ptr[N] = E;
    }
}

__global__ void scatter_kernel(const int* __restrict__ er, const int* __restrict__ ec,
                               const float* __restrict__ ev,
                               int* __restrict__ cur, int2* __restrict__ csr, int E) {
    int e = blockIdx.x * blockDim.x + threadIdx.x;
    if (e < E) {
        int pos = atomicAdd(&cur[er[e]], 1);
        csr[pos] = make_int2(ec[e], __float_as_int(ev[e]));
    }
}

// ---------------------------------------------------------------------------
// CSR SpMM: O[r,:] = sum_e val * D[col,:]  (64 cols). No atomics, no shfl.
// Half-warp per row; lane owns one float4. Edge meta read via uniform-address
// LDG.64 (warp broadcast, sequential -> L1 hits), unrolled x4 for MLP.
// ---------------------------------------------------------------------------
__global__ void csr_spmm_kernel(const int* __restrict__ ptr, const int2* __restrict__ csr,
                                const float* __restrict__ D, float* __restrict__ O, int N) {
    const int lane = threadIdx.x & 31;
    const int g = lane >> 4;          // row select within warp
    const int h = lane & 15;          // float4 chunk within row
    const int warpId = (blockIdx.x * blockDim.x + threadIdx.x) >> 5;
    const int row = warpId * 2 + g;
    if (row >= N) return;

    const int start = ptr[row];
    const int end   = ptr[row + 1];

    float4 acc = make_float4(0.f, 0.f, 0.f, 0.f);
    int j = start;

    for (; j + 4 <= end; j += 4) {
        const int2 m0 = __ldg(&csr[j]);
        const int2 m1 = __ldg(&csr[j + 1]);
        const int2 m2 = __ldg(&csr[j + 2]);
        const int2 m3 = __ldg(&csr[j + 3]);
        const float4 a0 = *(reinterpret_cast<const float4*>(D + (size_t)m0.x * 64) + h);
        const float4 a1 = *(reinterpret_cast<const float4*>(D + (size_t)m1.x * 64) + h);
        const float4 a2 = *(reinterpret_cast<const float4*>(D + (size_t)m2.x * 64) + h);
        const float4 a3 = *(reinterpret_cast<const float4*>(D + (size_t)m3.x * 64) + h);
        const float v0 = __int_as_float(m0.y), v1 = __int_as_float(m1.y);
        const float v2 = __int_as_float(m2.y), v3 = __int_as_float(m3.y);
        acc.x += v0 * a0.x; acc.y += v0 * a0.y; acc.z += v0 * a0.z; acc.w += v0 * a0.w;
        acc.x += v1 * a1.x; acc.y += v1 * a1.y; acc.z += v1 * a1.z; acc.w += v1 * a1.w;
        acc.x += v2 * a2.x; acc.y += v2 * a2.y; acc.z += v2 * a2.z; acc.w += v2 * a2.w;
        acc.x += v3 * a3.x; acc.y += v3 * a3.y; acc.z += v3 * a3.z; acc.w += v3 * a3.w;
    }
    for (; j < end; j++) {
        const int2 m = __ldg(&csr[j]);
        const float v = __int_as_float(m.y);
        const float4 a = *(reinterpret_cast<const float4*>(D + (size_t)m.x * 64) + h);
        acc.x += v * a.x; acc.y += v * a.y; acc.z += v * a.z; acc.w += v * a.w;
    }

    *(reinterpret_cast<float4*>(O + (size_t)row * 64) + h) = acc;
}

// ---------------------------------------------------------------------------
// Tiled GEMM (conflict-free smem): C = act(X)@W + b
// 64x64 tile, 256 threads, 4x4 per thread, Xs stride 33.
// ---------------------------------------------------------------------------
template<int K, bool RELU>
__global__ void gemm64_kernel(const float* __restrict__ X,
                              const float* __restrict__ W,
                              const float* __restrict__ b,
                              float* __restrict__ C, int N) {
    constexpr int BK = 32;
    __shared__ float Xs[64][BK + 1];   // stride 33: row-step 4 -> bank shift 4
    __shared__ float Ws[BK][64];

    const int tid = threadIdx.x;
    const int tx = tid & 15;
    const int ty = tid >> 4;
    const int nodeBase = blockIdx.x * 64;

    float acc[4][4];
    const float4 bv = *reinterpret_cast<const float4*>(b + tx * 4);
#pragma unroll
    for (int i = 0; i < 4; i++) {
        acc[i][0] = bv.x; acc[i][1] = bv.y; acc[i][2] = bv.z; acc[i][3] = bv.w;
    }

    for (int kc = 0; kc < K; kc += BK) {
#pragma unroll
        for (int t = 0; t < 2; t++) {
            int idx = tid + t * 256;          // 0..511
            int r   = idx >> 3;               // 0..63
            int c4  = idx & 7;                // 0..7
            int node = nodeBase + r;
            float4 xv = make_float4(0.f, 0.f, 0.f, 0.f);
            if (node < N)
                xv = *reinterpret_cast<const float4*>(X + (size_t)node * K + kc + c4 * 4);
            if (RELU) {
                xv.x = fmaxf(xv.x, 0.f); xv.y = fmaxf(xv.y, 0.f);
                xv.z = fmaxf(xv.z, 0.f); xv.w = fmaxf(xv.w, 0.f);
            }
            Xs[r][c4 * 4 + 0] = xv.x;
            Xs[r][c4 * 4 + 1] = xv.y;
            Xs[r][c4 * 4 + 2] = xv.z;
            Xs[r][c4 * 4 + 3] = xv.w;
        }
#pragma unroll
        for (int t = 0; t < 2; t++) {
            int idx = tid + t * 256;
            int r   = idx >> 4;               // 0..31
            int c4  = idx & 15;               // 0..15
            *reinterpret_cast<float4*>(&Ws[r][c4 * 4]) =
                *reinterpret_cast<const float4*>(W + (size_t)(kc + r) * 64 + c4 * 4);
        }
        __syncthreads();

#pragma unroll
        for (int kk = 0; kk < BK; kk++) {
            const float4 wv = *reinterpret_cast<const float4*>(&Ws[kk][tx * 4]);
            float xv[4];
#pragma unroll
            for (int i = 0; i < 4; i++) xv[i] = Xs[ty * 4 + i][kk];
#pragma unroll
            for (int i = 0; i < 4; i++) {
                acc[i][0] += xv[i] * wv.x;
                acc[i][1] += xv[i] * wv.y;
                acc[i][2] += xv[i] * wv.z;
                acc[i][3] += xv[i] * wv.w;
            }
        }
        __syncthreads();
    }

#pragma unroll
    for (int i = 0; i < 4; i++) {
        int node = nodeBase + ty * 4 + i;
        if (node < N) {
            float4 o = make_float4(acc[i][0], acc[i][1], acc[i][2], acc[i][3]);
            *reinterpret_cast<float4*>(C + (size_t)node * 64 + tx * 4) = o;
        }
    }
}

// ---------------------------------------------------------------------------
// Classifier: out = log_softmax(H @ Wc + bc), one warp per node.
// ---------------------------------------------------------------------------
__global__ void classifier_kernel(const float* __restrict__ H,
                                  const float* __restrict__ Wc,
                                  const float* __restrict__ bc,
                                  float* __restrict__ out, int N) {
    __shared__ float Ws[64 * 40 + 64];
    __shared__ float bs[40];
    __shared__ float hs[8][64];

    const int tid  = threadIdx.x;
    const int lane = tid & 31;
    const int warp = tid >> 5;

    for (int i = tid; i < 64 * 40; i += 256) Ws[i] = Wc[i];
    for (int i = 64 * 40 + tid; i < 64 * 40 + 64; i += 256) Ws[i] = 0.f;
    if (tid < 40) bs[tid] = bc[tid];
    __syncthreads();

    for (int it = 0; it < 4; it++) {
        const int node = blockIdx.x * 32 + it * 8 + warp;
        if (node < N) {
            __syncwarp();
            hs[warp][lane]      = H[(size_t)node * 64 + lane];
            hs[warp][lane + 32] = H[(size_t)node * 64 + lane + 32];
            __syncwarp();

            float v0 = bs[lane];
            float v1 = (lane < 8) ? bs[32 + lane] : 0.f;
#pragma unroll
            for (int k = 0; k < 64; k++) {
                const float h = hs[warp][k];
                v0 += h * Ws[k * 40 + lane];
                v1 += h * Ws[k * 40 + 32 + lane];
            }

            float m = (lane < 8) ? fmaxf(v0, v1) : v0;
#pragma unroll
            for (int off = 16; off; off >>= 1)
                m = fmaxf(m, __shfl_xor_sync(0xffffffffu, m, off));
            float s = expf(v0 - m) + ((lane < 8) ? expf(v1 - m) : 0.f);
#pragma unroll
            for (int off = 16; off; off >>= 1)
                s += __shfl_xor_sync(0xffffffffu, s, off);
            const float lse = m + logf(s);

            out[(size_t)node * 40 + lane] = v0 - lse;
            if (lane < 8)
                out[(size_t)node * 40 + 32 + lane] = v1 - lse;
        }
    }
}

// ---------------------------------------------------------------------------
// launch
// ---------------------------------------------------------------------------
extern "C" void kernel_launch(void* const* d_in, const int* in_sizes, int n_in,
                              void* d_out, int out_size) {
    const float* x  = (const float*)d_in[0];
    const int*   er = (const int*)  d_in[1];
    const int*   ec = (const int*)  d_in[2];
    const float* ev = (const float*)d_in[3];
    const float* W1 = (const float*)d_in[4];
    const float* b1 = (const float*)d_in[5];
    const float* W2 = (const float*)d_in[6];
    const float* b2 = (const float*)d_in[7];
    const float* Wc = (const float*)d_in[8];
    const float* bc = (const float*)d_in[9];
    float* out = (float*)d_out;

    const int N = in_sizes[0] / IN_DIM;   // 100000
    const int E = in_sizes[1];            // 1600000

    void *pA_, *pB_, *pCnt_, *pPtr_, *pPar_, *pCsr_;
    cudaGetSymbolAddress(&pA_, g_A);
    cudaGetSymbolAddress(&pB_, g_B);
    cudaGetSymbolAddress(&pCnt_, g_cnt);
    cudaGetSymbolAddress(&pPtr_, g_ptr);
    cudaGetSymbolAddress(&pPar_, g_partials);
    cudaGetSymbolAddress(&pCsr_, g_csr);
    float* A   = (float*)pA_;
    float* B   = (float*)pB_;
    int*   cnt = (int*)pCnt_;
    int*   ptr = (int*)pPtr_;
    int*   par = (int*)pPar_;
    int2*  csr = (int2*)pCsr_;

    const int gemmBlocks = (N + 63) / 64;
    const int eBlocks    = (E + 255) / 256;
    const int spmmBlocks = (N + 15) / 16;      // 16 rows per 256-thread block
    const int clsBlocks  = (N + 31) / 32;

    // --- CSR build (per launch; no caching) ---
    zero_int_kernel<<<(N + 255) / 256, 256>>>(cnt, N);
    hist_kernel<<<eBlocks, 256>>>(er, cnt, E);
    chunk_reduce_kernel<<<NCHUNK, CHUNK>>>(cnt, par, N);
    block_scan_kernel<<<NCHUNK, CHUNK>>>(cnt, par, ptr, cnt /*cursor reuses cnt*/, N, E);
    scatter_kernel<<<eBlocks, 256>>>(er, ec, ev, cnt, csr, E);

    // --- Layer 1 ---
    gemm64_kernel<IN_DIM, false><<<gemmBlocks, 256>>>(x, W1, b1, A, N);
    csr_spmm_kernel<<<spmmBlocks, 256>>>(ptr, csr, A, B, N);

    // --- Layer 2 (relu fused into GEMM read) ---
    gemm64_kernel<HID, true><<<gemmBlocks, 256>>>(B, W2, b2, A, N);
    csr_spmm_kernel<<<spmmBlocks, 256>>>(ptr, csr, A, B, N);

    // --- Classifier + log-softmax ---
    classifier_kernel<<<clsBlocks, 256>>>(B, Wc, bc, out, N);
}